// round 4
// baseline (speedup 1.0000x reference)
#include <cuda_runtime.h>
#include <math.h>

// Problem constants (fixed by dataset)
#define T     32768
#define H     1024
#define NH    12
#define KD    768
#define VD    1536
#define HK    64
#define HV    128
#define NSEG  16
#define DIN   16
#define ACD   32
#define XAW   48
#define NPACK 2328   // KD + VD + 2*NH
#define LDC   2432   // 19*128, padded N for the fused projection GEMM

// ----------------------------------------------------------------------------
// Device scratch (static, no allocations)
// ----------------------------------------------------------------------------
__device__ float g_xa[(size_t)T * XAW];          // [x | ac[seg]]   (T,48)
__device__ int   g_segid[T];
__device__ float g_c2[(size_t)T * H];            // XA @ W_in (pre-bias)
__device__ float g_hn[(size_t)T * H];            // rmsnorm output
__device__ float g_resid[NSEG * H];              // h at pooled rows (pre-norm)
__device__ float g_Bpack[(size_t)H * LDC];       // [Wk | Wv | Wb | Wa | 0pad]
__device__ float g_C[(size_t)T * LDC];           // hn @ Bpack
__device__ float g_k[(size_t)T * KD];            // conv+silu(+l2norm) k
__device__ float g_v[(size_t)T * VD];            // conv+silu v
__device__ float g_decay[(size_t)T * NH];        // exp(g_t)
__device__ float g_beta[(size_t)T * NH];
__device__ float g_S[NSEG * NH * HK * HV];       // final states per (seg,head)

// ----------------------------------------------------------------------------
// K0: pack B = [Wk | Wv | Wb | Wa] into a single (1024 x 2432) matrix
// ----------------------------------------------------------------------------
__global__ void k_pack(const float* __restrict__ Wk, const float* __restrict__ Wv,
                       const float* __restrict__ Wb, const float* __restrict__ Wa) {
    int idx = blockIdx.x * 256 + threadIdx.x;
    if (idx >= H * LDC) return;
    int k = idx / LDC, n = idx % LDC;
    float v = 0.f;
    if      (n < KD)           v = Wk[k * KD + n];
    else if (n < KD + VD)      v = Wv[k * VD + (n - KD)];
    else if (n < KD + VD + NH) v = Wb[k * NH + (n - KD - VD)];
    else if (n < NPACK)        v = Wa[k * NH + (n - KD - VD - NH)];
    g_Bpack[idx] = v;
}

// ----------------------------------------------------------------------------
// K1a: build XA = [x, ac_table[aidx[seg]]] and seg_id
// ----------------------------------------------------------------------------
__global__ void k_xa(const float* __restrict__ x, const int* __restrict__ cu,
                     const int* __restrict__ aidx, const float* __restrict__ ac) {
    int t = blockIdx.x * blockDim.x + threadIdx.x;
    if (t >= T) return;
    int seg = 0;
    #pragma unroll
    for (int s = 1; s < NSEG; ++s) if (t >= cu[s]) seg = s;
    g_segid[t] = seg;
    int a = aidx[seg];
    float* dst = g_xa + (size_t)t * XAW;
    const float* xr = x + (size_t)t * DIN;
    #pragma unroll
    for (int j = 0; j < DIN; ++j) dst[j] = xr[j];
    const float* ar = ac + (size_t)a * ACD;
    #pragma unroll
    for (int j = 0; j < ACD; ++j) dst[DIN + j] = ar[j];
}

// ----------------------------------------------------------------------------
// Generic fp32 SGEMM: C = A(MxK,lda) * B(KxN,ldb).
// Tiles 128x128x16, 256 threads. Thread (tr,tc) in a 16x16 grid computes the
// 8x8 microtile at rows {tr*4+0..3, tr*4+64..67} x cols {tc*4+0..3, tc*4+64..67}
// -> exact bijective cover of the 128x128 tile.
// Requires: M%128==0, N%128==0, K%16==0 (true for all call sites).
// ----------------------------------------------------------------------------
__global__ __launch_bounds__(256) void gemm128(const float* __restrict__ A, int lda,
                                               const float* __restrict__ B, int ldb,
                                               float* __restrict__ C, int ldc, int Kdim) {
    __shared__ __align__(16) float As[16][128];
    __shared__ __align__(16) float Bs[16][128];
    int tid = threadIdx.x;
    int bm0 = blockIdx.y * 128, bn0 = blockIdx.x * 128;

    int aR = tid >> 2, aC = (tid & 3) << 2;     // A tile: rows (aR, aR+64), float4 at k-col aC
    int bR = tid >> 5, bC = (tid & 31) << 2;    // B tile: k-rows (bR, bR+8), float4 at col bC

    const float* Ap = A + (size_t)(bm0 + aR) * lda + aC;
    const float* Bp = B + (size_t)bR * ldb + bn0 + bC;

    float4 pa0 = *(const float4*)Ap;
    float4 pa1 = *(const float4*)(Ap + (size_t)64 * lda);
    float4 pb0 = *(const float4*)Bp;
    float4 pb1 = *(const float4*)(Bp + (size_t)8 * ldb);

    int tr = tid >> 4, tc = tid & 15;           // 16x16 thread grid
    int am = tr * 4;                            // rows am..am+3 and am+64..am+67
    int bn = tc * 4;                            // cols bn..bn+3 and bn+64..bn+67

    float acc[8][8];
    #pragma unroll
    for (int i = 0; i < 8; ++i)
        #pragma unroll
        for (int j = 0; j < 8; ++j) acc[i][j] = 0.f;

    int nk = Kdim >> 4;
    for (int kt = 0; kt < nk; ++kt) {
        As[aC + 0][aR]      = pa0.x; As[aC + 1][aR]      = pa0.y;
        As[aC + 2][aR]      = pa0.z; As[aC + 3][aR]      = pa0.w;
        As[aC + 0][aR + 64] = pa1.x; As[aC + 1][aR + 64] = pa1.y;
        As[aC + 2][aR + 64] = pa1.z; As[aC + 3][aR + 64] = pa1.w;
        *(float4*)&Bs[bR][bC]     = pb0;
        *(float4*)&Bs[bR + 8][bC] = pb1;
        __syncthreads();

        if (kt + 1 < nk) {
            Ap += 16; Bp += (size_t)16 * ldb;
            pa0 = *(const float4*)Ap;
            pa1 = *(const float4*)(Ap + (size_t)64 * lda);
            pb0 = *(const float4*)Bp;
            pb1 = *(const float4*)(Bp + (size_t)8 * ldb);
        }

        #pragma unroll
        for (int kk = 0; kk < 16; ++kk) {
            float4 a0 = *(const float4*)&As[kk][am];
            float4 a1 = *(const float4*)&As[kk][am + 64];
            float4 b0 = *(const float4*)&Bs[kk][bn];
            float4 b1 = *(const float4*)&Bs[kk][bn + 64];
            float av[8] = {a0.x, a0.y, a0.z, a0.w, a1.x, a1.y, a1.z, a1.w};
            float bv[8] = {b0.x, b0.y, b0.z, b0.w, b1.x, b1.y, b1.z, b1.w};
            #pragma unroll
            for (int i = 0; i < 8; ++i)
                #pragma unroll
                for (int j = 0; j < 8; ++j)
                    acc[i][j] += av[i] * bv[j];
        }
        __syncthreads();
    }

    #pragma unroll
    for (int i = 0; i < 8; ++i) {
        int row = bm0 + am + ((i < 4) ? i : (60 + i));   // +0..3 / +64..67
        float4 v0 = make_float4(acc[i][0], acc[i][1], acc[i][2], acc[i][3]);
        float4 v1 = make_float4(acc[i][4], acc[i][5], acc[i][6], acc[i][7]);
        *(float4*)(C + (size_t)row * ldc + bn0 + bn)      = v0;
        *(float4*)(C + (size_t)row * ldc + bn0 + bn + 64) = v1;
    }
}

// ----------------------------------------------------------------------------
// K1c: h = c2 + b_in ; rmsnorm -> hn ; stash residual at pooled rows
// ----------------------------------------------------------------------------
__global__ void k_rms(const float* __restrict__ b_in, const float* __restrict__ norm_w,
                      const int* __restrict__ cu) {
    int t = blockIdx.x, tid = threadIdx.x;
    const float* row = g_c2 + (size_t)t * H;
    float vals[4];
    float ss = 0.f;
    #pragma unroll
    for (int i = 0; i < 4; ++i) {
        int c = tid + i * 256;
        float v = row[c] + b_in[c];
        vals[i] = v;
        ss += v * v;
    }
    #pragma unroll
    for (int o = 16; o > 0; o >>= 1) ss += __shfl_xor_sync(0xffffffffu, ss, o);
    __shared__ float wred[8];
    if ((tid & 31) == 0) wred[tid >> 5] = ss;
    __syncthreads();
    float tot = 0.f;
    #pragma unroll
    for (int j = 0; j < 8; ++j) tot += wred[j];
    float r = rsqrtf(tot / (float)H + 1e-6f);
    int seg = g_segid[t];
    bool isLast = (t == cu[seg + 1] - 1);
    #pragma unroll
    for (int i = 0; i < 4; ++i) {
        int c = tid + i * 256;
        g_hn[(size_t)t * H + c] = vals[i] * r * (1.f + norm_w[c]);
        if (isLast) g_resid[seg * H + c] = vals[i];
    }
}

// ----------------------------------------------------------------------------
// K3a: causal segment-masked short conv (width 4) + silu for k and v channels
// ----------------------------------------------------------------------------
__global__ void k_conv(const float* __restrict__ conv_kw, const float* __restrict__ conv_vw) {
    int t = blockIdx.y;
    int c = blockIdx.x * 256 + threadIdx.x;
    if (c >= KD + VD) return;
    int seg = g_segid[t];
    const float* wp = (c < KD) ? (conv_kw + (size_t)c * 4) : (conv_vw + (size_t)(c - KD) * 4);
    float out = 0.f;
    #pragma unroll
    for (int s = 0; s < 4; ++s) {
        int ts = t - s;
        if (ts >= 0 && g_segid[ts] == seg)
            out += wp[3 - s] * g_C[(size_t)ts * LDC + c];
    }
    float sv = out / (1.f + expf(-out));   // silu
    if (c < KD) g_k[(size_t)t * KD + c] = sv;
    else        g_v[(size_t)t * VD + (c - KD)] = sv;
}

// ----------------------------------------------------------------------------
// K3b: per-head l2norm of k (sum-of-squares + 1e-6, NOT mean)
// ----------------------------------------------------------------------------
__global__ void k_l2() {
    int t = blockIdx.x, c = threadIdx.x;   // 768 threads
    float v = g_k[(size_t)t * KD + c];
    float ss = v * v;
    #pragma unroll
    for (int o = 16; o > 0; o >>= 1) ss += __shfl_xor_sync(0xffffffffu, ss, o);
    __shared__ float ws[24];
    if ((c & 31) == 0) ws[c >> 5] = ss;
    __syncthreads();
    int h = c >> 6;
    float tot = ws[2 * h] + ws[2 * h + 1];
    g_k[(size_t)t * KD + c] = v * rsqrtf(tot + 1e-6f);
}

// ----------------------------------------------------------------------------
// K3c: beta = sigmoid(bpre), decay = exp(-exp(A_log)*softplus(apre+dt_bias))
// ----------------------------------------------------------------------------
__global__ void k_bd(const float* __restrict__ A_log, const float* __restrict__ dt_bias) {
    int idx = blockIdx.x * 256 + threadIdx.x;
    if (idx >= T * NH) return;
    int t = idx / NH, h = idx - t * NH;
    float bp = g_C[(size_t)t * LDC + (NPACK - 2 * NH) + h];
    float ap = g_C[(size_t)t * LDC + (NPACK - NH) + h] + dt_bias[h];
    g_beta[idx] = 1.f / (1.f + expf(-bp));
    float sp = (ap > 20.f) ? ap : log1pf(expf(ap));
    g_decay[idx] = expf(-expf(A_log[h]) * sp);
}

// ----------------------------------------------------------------------------
// K4: sequential gated-delta scan. One CTA per (segment, head); 128 threads,
// one per v-column; S[:,v] (64 floats) in registers. k staged via smem float4.
// Only the FINAL state per segment is needed (o is consumed only at seg ends).
// ----------------------------------------------------------------------------
__global__ __launch_bounds__(128) void k_scan(const int* __restrict__ cu) {
    int b = blockIdx.x;
    int seg = b / NH, h = b - seg * NH;
    int t0 = cu[seg], t1 = cu[seg + 1];
    int tid = threadIdx.x;                       // v column

    float S[HK];
    #pragma unroll
    for (int i = 0; i < HK; ++i) S[i] = 0.f;

    __shared__ __align__(16) float ks[16][HK];
    __shared__ float ds[16], bsh[16];

    for (int tc = t0; tc < t1; tc += 16) {
        int cnt = min(16, t1 - tc);
        for (int i = tid; i < cnt * 16; i += 128) {
            int tok = i >> 4, q = i & 15;
            ((float4*)ks[tok])[q] =
                *(const float4*)(g_k + (size_t)(tc + tok) * KD + h * HK + q * 4);
        }
        if (tid < 16) {
            if (tid < cnt) ds[tid] = g_decay[(size_t)(tc + tid) * NH + h];
        } else if (tid < 32) {
            int i2 = tid - 16;
            if (i2 < cnt) bsh[i2] = g_beta[(size_t)(tc + i2) * NH + h];
        }
        float vv[16];
        for (int i = 0; i < cnt; ++i)
            vv[i] = g_v[(size_t)(tc + i) * VD + h * HV + tid];
        __syncthreads();

        for (int i = 0; i < cnt; ++i) {
            float d = ds[i], bt = bsh[i], vt = vv[i];
            const float4* kp = (const float4*)ks[i];
            float d0 = 0.f, d1 = 0.f, d2 = 0.f, d3 = 0.f;
            #pragma unroll
            for (int q = 0; q < 16; ++q) {
                float4 k4 = kp[q];
                d0 += k4.x * S[4 * q + 0];
                d1 += k4.y * S[4 * q + 1];
                d2 += k4.z * S[4 * q + 2];
                d3 += k4.w * S[4 * q + 3];
            }
            float u = bt * (vt - d * ((d0 + d1) + (d2 + d3)));
            #pragma unroll
            for (int q = 0; q < 16; ++q) {
                float4 k4 = kp[q];
                S[4 * q + 0] = d * S[4 * q + 0] + k4.x * u;
                S[4 * q + 1] = d * S[4 * q + 1] + k4.y * u;
                S[4 * q + 2] = d * S[4 * q + 2] + k4.z * u;
                S[4 * q + 3] = d * S[4 * q + 3] + k4.w * u;
            }
        }
        __syncthreads();
    }

    float* Sp = g_S + (size_t)(seg * NH + h) * HK * HV + tid;
    #pragma unroll
    for (int i = 0; i < HK; ++i) Sp[i * HV] = S[i];
}

// ----------------------------------------------------------------------------
// K5: finalize — per segment: q (conv over last 4 rows), o = q.S_final,
// o-rmsnorm, swish gate, o@Wo + residual, head projection. 16 CTAs only.
// ----------------------------------------------------------------------------
__global__ __launch_bounds__(256) void k_final(
    const int* __restrict__ cu, const float* __restrict__ Wq,
    const float* __restrict__ conv_qw, const float* __restrict__ Wg,
    const float* __restrict__ o_norm_w, const float* __restrict__ Wo,
    const float* __restrict__ W_head, const float* __restrict__ b_head,
    float* __restrict__ out) {

    __shared__ float hnr[4][H];    // hn rows re-3..re
    __shared__ float qp[4][KD];    // q pre-activations
    __shared__ float qn[KD];       // q after conv+silu (then scaled on use)
    __shared__ float ov[VD];       // o vector (reused for gated o)
    __shared__ float red[NH];      // q per-head sum-of-squares
    __shared__ float red2[NH];     // o per-head sum-of-squares
    __shared__ float outred;

    int seg = blockIdx.x, tid = threadIdx.x;
    int start = cu[seg], re = cu[seg + 1] - 1;

    for (int i = tid; i < 4 * H; i += 256) {
        int rr = i >> 10, c = i & (H - 1);
        int row = re - 3 + rr;
        hnr[rr][c] = (row >= start) ? g_hn[(size_t)row * H + c] : 0.f;
    }
    if (tid < NH) { red[tid] = 0.f; red2[tid] = 0.f; }
    if (tid == 0) outred = 0.f;
    __syncthreads();

    // q pre-projection for the 4 lookback rows (shared Wq load, 4-way reuse)
    for (int c = tid; c < KD; c += 256) {
        float a0 = 0.f, a1 = 0.f, a2 = 0.f, a3 = 0.f;
        for (int k = 0; k < H; ++k) {
            float w = Wq[(size_t)k * KD + c];
            a0 += hnr[0][k] * w; a1 += hnr[1][k] * w;
            a2 += hnr[2][k] * w; a3 += hnr[3][k] * w;
        }
        qp[0][c] = a0; qp[1][c] = a1; qp[2][c] = a2; qp[3][c] = a3;
    }
    __syncthreads();

    // q conv + silu + per-head sumsq
    for (int c = tid; c < KD; c += 256) {
        float val = 0.f;
        #pragma unroll
        for (int s = 0; s < 4; ++s) {
            int row = re - s;
            if (row >= start) val += conv_qw[c * 4 + 3 - s] * qp[3 - s][c];
        }
        float sv = val / (1.f + expf(-val));
        qn[c] = sv;
        atomicAdd(&red[c >> 6], sv * sv);
    }
    __syncthreads();

    // o[h,v] = scale * l2norm(q_h) . S_final[h,:,v]
    for (int j = tid; j < VD; j += 256) {
        int h = j >> 7, v = j & 127;
        float qs = rsqrtf(red[h] + 1e-6f) * 0.125f;   // l2norm * HK^{-1/2}
        const float* Sp = g_S + (size_t)(seg * NH + h) * HK * HV + v;
        const float* qh = qn + h * HK;
        float acc = 0.f;
        #pragma unroll 8
        for (int kk = 0; kk < HK; ++kk) acc += qh[kk] * Sp[kk * HV];
        acc *= qs;
        ov[j] = acc;
        atomicAdd(&red2[h], acc * acc);
    }
    __syncthreads();

    // o-rmsnorm (mean, eps 1e-5) * o_norm_w, then swish gate (gate = hn@Wg row)
    for (int j = tid; j < VD; j += 256) {
        int h = j >> 7, v = j & 127;
        float on = ov[j] * rsqrtf(red2[h] / (float)HV + 1e-5f) * o_norm_w[v];
        float gacc = 0.f;
        for (int k = 0; k < H; ++k) gacc += hnr[3][k] * Wg[(size_t)k * VD + j];
        float og = on * gacc / (1.f + expf(-gacc));
        ov[j] = og;
    }
    __syncthreads();

    // h_final = ov @ Wo + residual; out[seg] = h_final . W_head + b_head
    float accs[4];
    #pragma unroll
    for (int i = 0; i < 4; ++i) accs[i] = g_resid[seg * H + tid + i * 256];
    for (int j = 0; j < VD; ++j) {
        float o = ov[j];
        #pragma unroll
        for (int i = 0; i < 4; ++i)
            accs[i] += o * Wo[(size_t)j * H + tid + i * 256];
    }
    float part = 0.f;
    #pragma unroll
    for (int i = 0; i < 4; ++i) part += accs[i] * W_head[tid + i * 256];
    #pragma unroll
    for (int o = 16; o > 0; o >>= 1) part += __shfl_xor_sync(0xffffffffu, part, o);
    if ((tid & 31) == 0) atomicAdd(&outred, part);
    __syncthreads();
    if (tid == 0) out[seg] = outred + b_head[0];
}

// ----------------------------------------------------------------------------
// Launcher (graph-capturable: kernel launches only)
// ----------------------------------------------------------------------------
extern "C" void kernel_launch(void* const* d_in, const int* in_sizes, int n_in,
                              void* d_out, int out_size) {
    const float* x        = (const float*)d_in[0];
    const int*   cu       = (const int*)  d_in[1];
    const int*   aidx     = (const int*)  d_in[2];
    const float* ac_table = (const float*)d_in[3];
    const float* W_in     = (const float*)d_in[4];
    const float* b_in     = (const float*)d_in[5];
    const float* norm_w   = (const float*)d_in[6];
    const float* Wq       = (const float*)d_in[7];
    const float* Wk       = (const float*)d_in[8];
    const float* Wv       = (const float*)d_in[9];
    const float* conv_qw  = (const float*)d_in[10];
    const float* conv_kw  = (const float*)d_in[11];
    const float* conv_vw  = (const float*)d_in[12];
    const float* Wb       = (const float*)d_in[13];
    const float* Wa       = (const float*)d_in[14];
    const float* A_log    = (const float*)d_in[15];
    const float* dt_bias  = (const float*)d_in[16];
    const float* Wg       = (const float*)d_in[17];
    const float* o_norm_w = (const float*)d_in[18];
    const float* Wo       = (const float*)d_in[19];
    const float* W_head   = (const float*)d_in[20];
    const float* b_head   = (const float*)d_in[21];
    float* out = (float*)d_out;

    void *p_xa, *p_c2, *p_hn, *p_B, *p_C;
    cudaGetSymbolAddress(&p_xa, g_xa);
    cudaGetSymbolAddress(&p_c2, g_c2);
    cudaGetSymbolAddress(&p_hn, g_hn);
    cudaGetSymbolAddress(&p_B,  g_Bpack);
    cudaGetSymbolAddress(&p_C,  g_C);

    // K0: pack projection weights
    k_pack<<<(H * LDC + 255) / 256, 256>>>(Wk, Wv, Wb, Wa);
    // K1a: XA + seg ids
    k_xa<<<(T + 127) / 128, 128>>>(x, cu, aidx, ac_table);
    // K1b: c2 = XA @ W_in   (M=32768, N=1024, K=48)
    gemm128<<<dim3(H / 128, T / 128), 256>>>((const float*)p_xa, XAW,
                                             W_in, H, (float*)p_c2, H, XAW);
    // K1c: bias + rmsnorm -> hn, residual rows
    k_rms<<<T, 256>>>(b_in, norm_w, cu);
    // K2: fused projections C = hn @ [Wk|Wv|Wb|Wa]  (M=32768, N=2432, K=1024)
    gemm128<<<dim3(LDC / 128, T / 128), 256>>>((const float*)p_hn, H,
                                               (const float*)p_B, LDC,
                                               (float*)p_C, LDC, H);
    // K3: conv+silu, l2norm(k), beta/decay
    k_conv<<<dim3((KD + VD + 255) / 256, T), 256>>>(conv_kw, conv_vw);
    k_l2<<<T, KD>>>();
    k_bd<<<(T * NH + 255) / 256, 256>>>(A_log, dt_bias);
    // K4: recurrent scan (final states only)
    k_scan<<<NSEG * NH, 128>>>(cu);
    // K5: finalize at pooled rows
    k_final<<<NSEG, 256>>>(cu, Wq, conv_qw, Wg, o_norm_w, Wo, W_head, b_head, out);
}

// round 8
// speedup vs baseline: 1.1628x; 1.1628x over previous
#include <cuda_runtime.h>
#include <cuda_bf16.h>
#include <math.h>

// Problem constants (fixed by dataset)
#define T     32768
#define H     1024
#define NH    12
#define KD    768
#define VD    1536
#define HK    64
#define HV    128
#define NSEG  16
#define DIN   16
#define ACD   32
#define XAW   48
#define NPACK 2328   // KD + VD + 2*NH
#define LDC   2432   // 19*128, padded N for the fused projection GEMM

// ----------------------------------------------------------------------------
// Device scratch (static, no allocations)
// ----------------------------------------------------------------------------
__device__ float g_xa[(size_t)T * XAW];          // [x | ac[seg]]   (T,48)
__device__ int   g_segid[T];
__device__ float g_c2[(size_t)T * H];            // XA @ W_in (pre-bias)
__device__ float g_hn[(size_t)T * H];            // rmsnorm output
__device__ float g_resid[NSEG * H];              // h at pooled rows (pre-norm)
__device__ __nv_bfloat16 g_Ahi[(size_t)T * H];   // bf16 hi of hn
__device__ __nv_bfloat16 g_Alo[(size_t)T * H];   // bf16 lo of hn
__device__ __nv_bfloat16 g_Bthi[(size_t)LDC * H];// transposed packed W, hi [n][k]
__device__ __nv_bfloat16 g_Btlo[(size_t)LDC * H];// transposed packed W, lo [n][k]
__device__ float g_C[(size_t)T * LDC];           // hn @ [Wk|Wv|Wb|Wa]
__device__ float g_k[(size_t)T * KD];            // conv+silu(+l2norm) k
__device__ float g_v[(size_t)T * VD];            // conv+silu v
__device__ float g_decay[(size_t)T * NH];        // exp(g_t)
__device__ float g_beta[(size_t)T * NH];
__device__ float g_S[NSEG * NH * HK * HV];       // final states per (seg,head)

// ----------------------------------------------------------------------------
// K0: pack + transpose + bf16-split B: Bt[n][k] = [Wk|Wv|Wb|Wa]^T
// ----------------------------------------------------------------------------
__global__ void k_packBt(const float* __restrict__ Wk, const float* __restrict__ Wv,
                         const float* __restrict__ Wb, const float* __restrict__ Wa) {
    int idx = blockIdx.x * 256 + threadIdx.x;
    if (idx >= LDC * H) return;
    int n = idx / H, k = idx - n * H;
    float v = 0.f;
    if      (n < KD)           v = Wk[k * KD + n];
    else if (n < KD + VD)      v = Wv[k * VD + (n - KD)];
    else if (n < KD + VD + NH) v = Wb[k * NH + (n - KD - VD)];
    else if (n < NPACK)        v = Wa[k * NH + (n - KD - VD - NH)];
    __nv_bfloat16 hi = __float2bfloat16(v);
    g_Bthi[idx] = hi;
    g_Btlo[idx] = __float2bfloat16(v - __bfloat162float(hi));
}

// ----------------------------------------------------------------------------
// K1a: build XA = [x, ac_table[aidx[seg]]] and seg_id
// ----------------------------------------------------------------------------
__global__ void k_xa(const float* __restrict__ x, const int* __restrict__ cu,
                     const int* __restrict__ aidx, const float* __restrict__ ac) {
    int t = blockIdx.x * blockDim.x + threadIdx.x;
    if (t >= T) return;
    int seg = 0;
    #pragma unroll
    for (int s = 1; s < NSEG; ++s) if (t >= cu[s]) seg = s;
    g_segid[t] = seg;
    int a = aidx[seg];
    float* dst = g_xa + (size_t)t * XAW;
    const float* xr = x + (size_t)t * DIN;
    #pragma unroll
    for (int j = 0; j < DIN; ++j) dst[j] = xr[j];
    const float* ar = ac + (size_t)a * ACD;
    #pragma unroll
    for (int j = 0; j < ACD; ++j) dst[DIN + j] = ar[j];
}

// ----------------------------------------------------------------------------
// Generic fp32 SGEMM (kept for the small K1b GEMM, K=48).
// ----------------------------------------------------------------------------
__global__ __launch_bounds__(256) void gemm128(const float* __restrict__ A, int lda,
                                               const float* __restrict__ B, int ldb,
                                               float* __restrict__ C, int ldc, int Kdim) {
    __shared__ __align__(16) float As[16][128];
    __shared__ __align__(16) float Bs[16][128];
    int tid = threadIdx.x;
    int bm0 = blockIdx.y * 128, bn0 = blockIdx.x * 128;

    int aR = tid >> 2, aC = (tid & 3) << 2;
    int bR = tid >> 5, bC = (tid & 31) << 2;

    const float* Ap = A + (size_t)(bm0 + aR) * lda + aC;
    const float* Bp = B + (size_t)bR * ldb + bn0 + bC;

    float4 pa0 = *(const float4*)Ap;
    float4 pa1 = *(const float4*)(Ap + (size_t)64 * lda);
    float4 pb0 = *(const float4*)Bp;
    float4 pb1 = *(const float4*)(Bp + (size_t)8 * ldb);

    int tr = tid >> 4, tc = tid & 15;
    int am = tr * 4, bn = tc * 4;

    float acc[8][8];
    #pragma unroll
    for (int i = 0; i < 8; ++i)
        #pragma unroll
        for (int j = 0; j < 8; ++j) acc[i][j] = 0.f;

    int nk = Kdim >> 4;
    for (int kt = 0; kt < nk; ++kt) {
        As[aC + 0][aR]      = pa0.x; As[aC + 1][aR]      = pa0.y;
        As[aC + 2][aR]      = pa0.z; As[aC + 3][aR]      = pa0.w;
        As[aC + 0][aR + 64] = pa1.x; As[aC + 1][aR + 64] = pa1.y;
        As[aC + 2][aR + 64] = pa1.z; As[aC + 3][aR + 64] = pa1.w;
        *(float4*)&Bs[bR][bC]     = pb0;
        *(float4*)&Bs[bR + 8][bC] = pb1;
        __syncthreads();

        if (kt + 1 < nk) {
            Ap += 16; Bp += (size_t)16 * ldb;
            pa0 = *(const float4*)Ap;
            pa1 = *(const float4*)(Ap + (size_t)64 * lda);
            pb0 = *(const float4*)Bp;
            pb1 = *(const float4*)(Bp + (size_t)8 * ldb);
        }

        #pragma unroll
        for (int kk = 0; kk < 16; ++kk) {
            float4 a0 = *(const float4*)&As[kk][am];
            float4 a1 = *(const float4*)&As[kk][am + 64];
            float4 b0 = *(const float4*)&Bs[kk][bn];
            float4 b1 = *(const float4*)&Bs[kk][bn + 64];
            float av[8] = {a0.x, a0.y, a0.z, a0.w, a1.x, a1.y, a1.z, a1.w};
            float bv[8] = {b0.x, b0.y, b0.z, b0.w, b1.x, b1.y, b1.z, b1.w};
            #pragma unroll
            for (int i = 0; i < 8; ++i)
                #pragma unroll
                for (int j = 0; j < 8; ++j)
                    acc[i][j] += av[i] * bv[j];
        }
        __syncthreads();
    }

    #pragma unroll
    for (int i = 0; i < 8; ++i) {
        int row = bm0 + am + ((i < 4) ? i : (60 + i));
        float4 v0 = make_float4(acc[i][0], acc[i][1], acc[i][2], acc[i][3]);
        float4 v1 = make_float4(acc[i][4], acc[i][5], acc[i][6], acc[i][7]);
        *(float4*)(C + (size_t)row * ldc + bn0 + bn)      = v0;
        *(float4*)(C + (size_t)row * ldc + bn0 + bn + 64) = v1;
    }
}

// ----------------------------------------------------------------------------
// K1c: h = c2 + b_in ; rmsnorm -> hn (fp32 + bf16 hi/lo); residual at pooled rows
// ----------------------------------------------------------------------------
__global__ void k_rms(const float* __restrict__ b_in, const float* __restrict__ norm_w,
                      const int* __restrict__ cu) {
    int t = blockIdx.x, tid = threadIdx.x;
    const float* row = g_c2 + (size_t)t * H;
    float vals[4];
    float ss = 0.f;
    #pragma unroll
    for (int i = 0; i < 4; ++i) {
        int c = tid + i * 256;
        float v = row[c] + b_in[c];
        vals[i] = v;
        ss += v * v;
    }
    #pragma unroll
    for (int o = 16; o > 0; o >>= 1) ss += __shfl_xor_sync(0xffffffffu, ss, o);
    __shared__ float wred[8];
    if ((tid & 31) == 0) wred[tid >> 5] = ss;
    __syncthreads();
    float tot = 0.f;
    #pragma unroll
    for (int j = 0; j < 8; ++j) tot += wred[j];
    float r = rsqrtf(tot / (float)H + 1e-6f);
    int seg = g_segid[t];
    bool isLast = (t == cu[seg + 1] - 1);
    #pragma unroll
    for (int i = 0; i < 4; ++i) {
        int c = tid + i * 256;
        float hn = vals[i] * r * (1.f + norm_w[c]);
        size_t idx = (size_t)t * H + c;
        g_hn[idx] = hn;
        __nv_bfloat16 hi = __float2bfloat16(hn);
        g_Ahi[idx] = hi;
        g_Alo[idx] = __float2bfloat16(hn - __bfloat162float(hi));
        if (isLast) g_resid[seg * H + c] = vals[i];
    }
}

// ----------------------------------------------------------------------------
// K2: split-bf16 tensor-core GEMM  C = hn @ Bpack  (M=T, N=LDC, K=H)
// A hi/lo: row-major [T][H] bf16. Bt hi/lo: [n][k] bf16 (transposed).
// CTA 128x128x16, 8 warps (4x2), warp tile 32x64.
// acc += Ahi*Bhi + Ahi*Blo + Alo*Bhi   (3x mma.sync.m16n8k16 bf16)
// ----------------------------------------------------------------------------
__device__ __forceinline__ void mma16816(float* c, const unsigned* a, const unsigned* b) {
    asm volatile(
        "mma.sync.aligned.m16n8k16.row.col.f32.bf16.bf16.f32 "
        "{%0,%1,%2,%3}, {%4,%5,%6,%7}, {%8,%9}, {%0,%1,%2,%3};"
        : "+f"(c[0]), "+f"(c[1]), "+f"(c[2]), "+f"(c[3])
        : "r"(a[0]), "r"(a[1]), "r"(a[2]), "r"(a[3]), "r"(b[0]), "r"(b[1]));
}

__global__ __launch_bounds__(256) void gemm_bf16split() {
    __shared__ __align__(16) __nv_bfloat16 Ah[128][16];
    __shared__ __align__(16) __nv_bfloat16 Al[128][16];
    __shared__ __align__(16) __nv_bfloat16 Bh[128][16];
    __shared__ __align__(16) __nv_bfloat16 Bl[128][16];

    int tid = threadIdx.x;
    int bm0 = blockIdx.y * 128, bn0 = blockIdx.x * 128;

    int r = tid >> 1, half = tid & 1;        // loader: row r, 16B half
    size_t aoff = (size_t)(bm0 + r) * H + half * 8;
    size_t boff = (size_t)(bn0 + r) * H + half * 8;

    uint4 pah = *(const uint4*)(g_Ahi + aoff);
    uint4 pal = *(const uint4*)(g_Alo + aoff);
    uint4 pbh = *(const uint4*)(g_Bthi + boff);
    uint4 pbl = *(const uint4*)(g_Btlo + boff);

    int wid = tid >> 5, lane = tid & 31;
    int wm = wid & 3, wn = wid >> 2;          // 4x2 warp grid
    int grp = lane >> 2, qid = lane & 3;
    int mbase = wm * 32;                      // + mi*16
    int nbase = wn * 64;                      // + ni*8

    float acc[2][8][4];
    #pragma unroll
    for (int mi = 0; mi < 2; ++mi)
        #pragma unroll
        for (int ni = 0; ni < 8; ++ni)
            #pragma unroll
            for (int q = 0; q < 4; ++q) acc[mi][ni][q] = 0.f;

    const int NK = H / 16;   // 64
    for (int kt = 0; kt < NK; ++kt) {
        *(uint4*)&Ah[r][half * 8] = pah;
        *(uint4*)&Al[r][half * 8] = pal;
        *(uint4*)&Bh[r][half * 8] = pbh;
        *(uint4*)&Bl[r][half * 8] = pbl;
        __syncthreads();

        if (kt + 1 < NK) {
            aoff += 16; boff += 16;
            pah = *(const uint4*)(g_Ahi + aoff);
            pal = *(const uint4*)(g_Alo + aoff);
            pbh = *(const uint4*)(g_Bthi + boff);
            pbl = *(const uint4*)(g_Btlo + boff);
        }

        // fragments
        unsigned ah[2][4], al[2][4];
        #pragma unroll
        for (int mi = 0; mi < 2; ++mi) {
            int m0 = mbase + mi * 16 + grp;
            ah[mi][0] = *(const unsigned*)&Ah[m0][2 * qid];
            ah[mi][1] = *(const unsigned*)&Ah[m0 + 8][2 * qid];
            ah[mi][2] = *(const unsigned*)&Ah[m0][2 * qid + 8];
            ah[mi][3] = *(const unsigned*)&Ah[m0 + 8][2 * qid + 8];
            al[mi][0] = *(const unsigned*)&Al[m0][2 * qid];
            al[mi][1] = *(const unsigned*)&Al[m0 + 8][2 * qid];
            al[mi][2] = *(const unsigned*)&Al[m0][2 * qid + 8];
            al[mi][3] = *(const unsigned*)&Al[m0 + 8][2 * qid + 8];
        }
        #pragma unroll
        for (int ni = 0; ni < 8; ++ni) {
            int n0 = nbase + ni * 8 + grp;
            unsigned bh[2], bl[2];
            bh[0] = *(const unsigned*)&Bh[n0][2 * qid];
            bh[1] = *(const unsigned*)&Bh[n0][2 * qid + 8];
            bl[0] = *(const unsigned*)&Bl[n0][2 * qid];
            bl[1] = *(const unsigned*)&Bl[n0][2 * qid + 8];
            #pragma unroll
            for (int mi = 0; mi < 2; ++mi) {
                mma16816(acc[mi][ni], ah[mi], bh);   // hi*hi
                mma16816(acc[mi][ni], ah[mi], bl);   // hi*lo
                mma16816(acc[mi][ni], al[mi], bh);   // lo*hi
            }
        }
        __syncthreads();
    }

    // epilogue: c0,c1 -> row grp, cols 2q,2q+1 ; c2,c3 -> row grp+8
    #pragma unroll
    for (int mi = 0; mi < 2; ++mi) {
        int row0 = bm0 + mbase + mi * 16 + grp;
        #pragma unroll
        for (int ni = 0; ni < 8; ++ni) {
            int col = bn0 + nbase + ni * 8 + qid * 2;
            float2 v0 = make_float2(acc[mi][ni][0], acc[mi][ni][1]);
            float2 v1 = make_float2(acc[mi][ni][2], acc[mi][ni][3]);
            *(float2*)(g_C + (size_t)row0 * LDC + col)       = v0;
            *(float2*)(g_C + (size_t)(row0 + 8) * LDC + col) = v1;
        }
    }
}

// ----------------------------------------------------------------------------
// K3a: causal segment-masked short conv (width 4) + silu for k and v channels
// ----------------------------------------------------------------------------
__global__ void k_conv(const float* __restrict__ conv_kw, const float* __restrict__ conv_vw) {
    int t = blockIdx.y;
    int c = blockIdx.x * 256 + threadIdx.x;
    if (c >= KD + VD) return;
    int seg = g_segid[t];
    const float* wp = (c < KD) ? (conv_kw + (size_t)c * 4) : (conv_vw + (size_t)(c - KD) * 4);
    float out = 0.f;
    #pragma unroll
    for (int s = 0; s < 4; ++s) {
        int ts = t - s;
        if (ts >= 0 && g_segid[ts] == seg)
            out += wp[3 - s] * g_C[(size_t)ts * LDC + c];
    }
    float sv = out / (1.f + expf(-out));   // silu
    if (c < KD) g_k[(size_t)t * KD + c] = sv;
    else        g_v[(size_t)t * VD + (c - KD)] = sv;
}

// ----------------------------------------------------------------------------
// K3b: per-head l2norm of k (sum-of-squares + 1e-6, NOT mean)
// ----------------------------------------------------------------------------
__global__ void k_l2() {
    int t = blockIdx.x, c = threadIdx.x;   // 768 threads
    float v = g_k[(size_t)t * KD + c];
    float ss = v * v;
    #pragma unroll
    for (int o = 16; o > 0; o >>= 1) ss += __shfl_xor_sync(0xffffffffu, ss, o);
    __shared__ float ws[24];
    if ((c & 31) == 0) ws[c >> 5] = ss;
    __syncthreads();
    int h = c >> 6;
    float tot = ws[2 * h] + ws[2 * h + 1];
    g_k[(size_t)t * KD + c] = v * rsqrtf(tot + 1e-6f);
}

// ----------------------------------------------------------------------------
// K3c: beta = sigmoid(bpre), decay = exp(-exp(A_log)*softplus(apre+dt_bias))
// ----------------------------------------------------------------------------
__global__ void k_bd(const float* __restrict__ A_log, const float* __restrict__ dt_bias) {
    int idx = blockIdx.x * 256 + threadIdx.x;
    if (idx >= T * NH) return;
    int t = idx / NH, h = idx - t * NH;
    float bp = g_C[(size_t)t * LDC + (NPACK - 2 * NH) + h];
    float ap = g_C[(size_t)t * LDC + (NPACK - NH) + h] + dt_bias[h];
    g_beta[idx] = 1.f / (1.f + expf(-bp));
    float sp = (ap > 20.f) ? ap : log1pf(expf(ap));
    g_decay[idx] = expf(-expf(A_log[h]) * sp);
}

// ----------------------------------------------------------------------------
// K4: sequential gated-delta scan. One CTA per (segment, head); 128 threads,
// one per v-column; S[:,v] (64 floats) in registers.
// ----------------------------------------------------------------------------
__global__ __launch_bounds__(128) void k_scan(const int* __restrict__ cu) {
    int b = blockIdx.x;
    int seg = b / NH, h = b - seg * NH;
    int t0 = cu[seg], t1 = cu[seg + 1];
    int tid = threadIdx.x;                       // v column

    float S[HK];
    #pragma unroll
    for (int i = 0; i < HK; ++i) S[i] = 0.f;

    __shared__ __align__(16) float ks[16][HK];
    __shared__ float ds[16], bsh[16];

    for (int tc = t0; tc < t1; tc += 16) {
        int cnt = min(16, t1 - tc);
        for (int i = tid; i < cnt * 16; i += 128) {
            int tok = i >> 4, q = i & 15;
            ((float4*)ks[tok])[q] =
                *(const float4*)(g_k + (size_t)(tc + tok) * KD + h * HK + q * 4);
        }
        if (tid < 16) {
            if (tid < cnt) ds[tid] = g_decay[(size_t)(tc + tid) * NH + h];
        } else if (tid < 32) {
            int i2 = tid - 16;
            if (i2 < cnt) bsh[i2] = g_beta[(size_t)(tc + i2) * NH + h];
        }
        float vv[16];
        for (int i = 0; i < cnt; ++i)
            vv[i] = g_v[(size_t)(tc + i) * VD + h * HV + tid];
        __syncthreads();

        for (int i = 0; i < cnt; ++i) {
            float d = ds[i], bt = bsh[i], vt = vv[i];
            const float4* kp = (const float4*)ks[i];
            float d0 = 0.f, d1 = 0.f, d2 = 0.f, d3 = 0.f;
            #pragma unroll
            for (int q = 0; q < 16; ++q) {
                float4 k4 = kp[q];
                d0 += k4.x * S[4 * q + 0];
                d1 += k4.y * S[4 * q + 1];
                d2 += k4.z * S[4 * q + 2];
                d3 += k4.w * S[4 * q + 3];
            }
            float u = bt * (vt - d * ((d0 + d1) + (d2 + d3)));
            #pragma unroll
            for (int q = 0; q < 16; ++q) {
                float4 k4 = kp[q];
                S[4 * q + 0] = d * S[4 * q + 0] + k4.x * u;
                S[4 * q + 1] = d * S[4 * q + 1] + k4.y * u;
                S[4 * q + 2] = d * S[4 * q + 2] + k4.z * u;
                S[4 * q + 3] = d * S[4 * q + 3] + k4.w * u;
            }
        }
        __syncthreads();
    }

    float* Sp = g_S + (size_t)(seg * NH + h) * HK * HV + tid;
    #pragma unroll
    for (int i = 0; i < HK; ++i) Sp[i * HV] = S[i];
}

// ----------------------------------------------------------------------------
// K5: finalize at pooled rows (16 CTAs)
// ----------------------------------------------------------------------------
__global__ __launch_bounds__(256) void k_final(
    const int* __restrict__ cu, const float* __restrict__ Wq,
    const float* __restrict__ conv_qw, const float* __restrict__ Wg,
    const float* __restrict__ o_norm_w, const float* __restrict__ Wo,
    const float* __restrict__ W_head, const float* __restrict__ b_head,
    float* __restrict__ out) {

    __shared__ float hnr[4][H];
    __shared__ float qp[4][KD];
    __shared__ float qn[KD];
    __shared__ float ov[VD];
    __shared__ float red[NH];
    __shared__ float red2[NH];
    __shared__ float outred;

    int seg = blockIdx.x, tid = threadIdx.x;
    int start = cu[seg], re = cu[seg + 1] - 1;

    for (int i = tid; i < 4 * H; i += 256) {
        int rr = i >> 10, c = i & (H - 1);
        int row = re - 3 + rr;
        hnr[rr][c] = (row >= start) ? g_hn[(size_t)row * H + c] : 0.f;
    }
    if (tid < NH) { red[tid] = 0.f; red2[tid] = 0.f; }
    if (tid == 0) outred = 0.f;
    __syncthreads();

    for (int c = tid; c < KD; c += 256) {
        float a0 = 0.f, a1 = 0.f, a2 = 0.f, a3 = 0.f;
        for (int k = 0; k < H; ++k) {
            float w = Wq[(size_t)k * KD + c];
            a0 += hnr[0][k] * w; a1 += hnr[1][k] * w;
            a2 += hnr[2][k] * w; a3 += hnr[3][k] * w;
        }
        qp[0][c] = a0; qp[1][c] = a1; qp[2][c] = a2; qp[3][c] = a3;
    }
    __syncthreads();

    for (int c = tid; c < KD; c += 256) {
        float val = 0.f;
        #pragma unroll
        for (int s = 0; s < 4; ++s) {
            int row = re - s;
            if (row >= start) val += conv_qw[c * 4 + 3 - s] * qp[3 - s][c];
        }
        float sv = val / (1.f + expf(-val));
        qn[c] = sv;
        atomicAdd(&red[c >> 6], sv * sv);
    }
    __syncthreads();

    for (int j = tid; j < VD; j += 256) {
        int h = j >> 7, v = j & 127;
        float qs = rsqrtf(red[h] + 1e-6f) * 0.125f;
        const float* Sp = g_S + (size_t)(seg * NH + h) * HK * HV + v;
        const float* qh = qn + h * HK;
        float acc = 0.f;
        #pragma unroll 8
        for (int kk = 0; kk < HK; ++kk) acc += qh[kk] * Sp[kk * HV];
        acc *= qs;
        ov[j] = acc;
        atomicAdd(&red2[h], acc * acc);
    }
    __syncthreads();

    for (int j = tid; j < VD; j += 256) {
        int h = j >> 7, v = j & 127;
        float on = ov[j] * rsqrtf(red2[h] / (float)HV + 1e-5f) * o_norm_w[v];
        float gacc = 0.f;
        for (int k = 0; k < H; ++k) gacc += hnr[3][k] * Wg[(size_t)k * VD + j];
        float og = on * gacc / (1.f + expf(-gacc));
        ov[j] = og;
    }
    __syncthreads();

    float accs[4];
    #pragma unroll
    for (int i = 0; i < 4; ++i) accs[i] = g_resid[seg * H + tid + i * 256];
    for (int j = 0; j < VD; ++j) {
        float o = ov[j];
        #pragma unroll
        for (int i = 0; i < 4; ++i)
            accs[i] += o * Wo[(size_t)j * H + tid + i * 256];
    }
    float part = 0.f;
    #pragma unroll
    for (int i = 0; i < 4; ++i) part += accs[i] * W_head[tid + i * 256];
    #pragma unroll
    for (int o = 16; o > 0; o >>= 1) part += __shfl_xor_sync(0xffffffffu, part, o);
    if ((tid & 31) == 0) atomicAdd(&outred, part);
    __syncthreads();
    if (tid == 0) out[seg] = outred + b_head[0];
}

// ----------------------------------------------------------------------------
// Launcher (graph-capturable: kernel launches only)
// ----------------------------------------------------------------------------
extern "C" void kernel_launch(void* const* d_in, const int* in_sizes, int n_in,
                              void* d_out, int out_size) {
    const float* x        = (const float*)d_in[0];
    const int*   cu       = (const int*)  d_in[1];
    const int*   aidx     = (const int*)  d_in[2];
    const float* ac_table = (const float*)d_in[3];
    const float* W_in     = (const float*)d_in[4];
    const float* b_in     = (const float*)d_in[5];
    const float* norm_w   = (const float*)d_in[6];
    const float* Wq       = (const float*)d_in[7];
    const float* Wk       = (const float*)d_in[8];
    const float* Wv       = (const float*)d_in[9];
    const float* conv_qw  = (const float*)d_in[10];
    const float* conv_kw  = (const float*)d_in[11];
    const float* conv_vw  = (const float*)d_in[12];
    const float* Wb       = (const float*)d_in[13];
    const float* Wa       = (const float*)d_in[14];
    const float* A_log    = (const float*)d_in[15];
    const float* dt_bias  = (const float*)d_in[16];
    const float* Wg       = (const float*)d_in[17];
    const float* o_norm_w = (const float*)d_in[18];
    const float* Wo       = (const float*)d_in[19];
    const float* W_head   = (const float*)d_in[20];
    const float* b_head   = (const float*)d_in[21];
    float* out = (float*)d_out;

    void *p_xa, *p_c2;
    cudaGetSymbolAddress(&p_xa, g_xa);
    cudaGetSymbolAddress(&p_c2, g_c2);

    // K0: pack + transpose + split projection weights to bf16 hi/lo
    k_packBt<<<(LDC * H + 255) / 256, 256>>>(Wk, Wv, Wb, Wa);
    // K1a: XA + seg ids
    k_xa<<<(T + 127) / 128, 128>>>(x, cu, aidx, ac_table);
    // K1b: c2 = XA @ W_in   (M=32768, N=1024, K=48) — small, fp32
    gemm128<<<dim3(H / 128, T / 128), 256>>>((const float*)p_xa, XAW,
                                             W_in, H, (float*)p_c2, H, XAW);
    // K1c: bias + rmsnorm -> hn (fp32 + bf16 hi/lo fused), residual rows
    k_rms<<<T, 256>>>(b_in, norm_w, cu);
    // K2: fused projections on tensor cores (split-bf16, 3 MMAs)
    gemm_bf16split<<<dim3(LDC / 128, T / 128), 256>>>();
    // K3: conv+silu, l2norm(k), beta/decay
    k_conv<<<dim3((KD + VD + 255) / 256, T), 256>>>(conv_kw, conv_vw);
    k_l2<<<T, KD>>>();
    k_bd<<<(T * NH + 255) / 256, 256>>>(A_log, dt_bias);
    // K4: recurrent scan (final states only)
    k_scan<<<NSEG * NH, 128>>>(cu);
    // K5: finalize at pooled rows
    k_final<<<NSEG, 256>>>(cu, Wq, conv_qw, Wg, o_norm_w, Wo, W_head, b_head, out);
}